// round 4
// baseline (speedup 1.0000x reference)
#include <cuda_runtime.h>
#include <cuda_bf16.h>

#define THICKNESS 0.00047f
#define MAX_V 1000000

// 16 MB padded vertex scratch: posw[i] = (x, y, z, _)
__device__ float4 g_posw[MAX_V];

__global__ void pad_pos_kernel(const float* __restrict__ pos, int V) {
    int i = blockIdx.x * blockDim.x + threadIdx.x;
    if (i >= V) return;
    // parity-aligned 12B read (pos + 3i is 8B-aligned iff i even)
    bool even = (i & 1) == 0;
    const float* base = pos + 3u * (unsigned)i;
    float2 ab = __ldg((const float2*)(base + (even ? 0 : 1)));
    float  c  = __ldg(base + (even ? 2 : 0));
    float x = even ? ab.x : c;
    float y = even ? ab.y : ab.x;
    float z = even ? c    : ab.y;
    g_posw[i] = make_float4(x, y, z, 0.0f);
}

__global__ void stvk_face_kernel(
    const int* __restrict__ faces,        // [F,3] int32
    const float* __restrict__ dminv,      // [F,2,2]
    const float* __restrict__ area,       // [F,1]
    const float* __restrict__ mu_p,       // [1]
    const float* __restrict__ lam_p,      // [1]
    float* __restrict__ per_vert,         // [V]
    float* __restrict__ loss,             // scalar or nullptr
    int F)
{
    int f = blockIdx.x * blockDim.x + threadIdx.x;
    float e = 0.0f;
    if (f < F) {
        // streaming faces row, evict-first; parity trick for 12B row
        bool feven = (f & 1) == 0;
        const int* frow = faces + 3u * (unsigned)f;
        int2 fab = __ldcs((const int2*)(frow + (feven ? 0 : 1)));
        int  fc  = __ldcs(frow + (feven ? 2 : 0));
        int i0 = feven ? fab.x : fc;
        int i1 = feven ? fab.y : fab.x;
        int i2 = feven ? fc    : fab.y;

        // single-sector 16B gathers (L2-resident)
        float4 p0 = __ldg(&g_posw[i0]);
        float4 p1 = __ldg(&g_posw[i1]);
        float4 p2 = __ldg(&g_posw[i2]);

        // Ds columns: d1 = v0 - v2, d2 = v1 - v2
        float d1x = p0.x - p2.x, d1y = p0.y - p2.y, d1z = p0.z - p2.z;
        float d2x = p1.x - p2.x, d2y = p1.y - p2.y, d2z = p1.z - p2.z;

        float4 dm = __ldcs((const float4*)(dminv) + f);
        float a = dm.x, b = dm.y, c = dm.z, d = dm.w;

        // Fg = Ds @ Dm_inv
        float F0x = d1x * a + d2x * c;
        float F0y = d1y * a + d2y * c;
        float F0z = d1z * a + d2z * c;
        float F1x = d1x * b + d2x * d;
        float F1y = d1y * b + d2y * d;
        float F1z = d1z * b + d2z * d;

        // Green strain (symmetric 2x2)
        float g00 = 0.5f * (F0x * F0x + F0y * F0y + F0z * F0z - 1.0f);
        float g01 = 0.5f * (F0x * F1x + F0y * F1y + F0z * F1z);
        float g11 = 0.5f * (F1x * F1x + F1y * F1y + F1z * F1z - 1.0f);
        float tr = g00 + g11;

        float mu = __ldg(mu_p);
        float lam = __ldg(lam_p);

        float s00 = mu * g00 + 0.5f * lam * tr;
        float s01 = mu * g01;
        float s11 = mu * g11 + 0.5f * lam * tr;

        float ed = s00 * g00 + 2.0f * s01 * g01 + s11 * g11;

        e = __ldcs(&area[f]) * THICKNESS * ed;

        float e3 = e * (1.0f / 3.0f);
        atomicAdd(&per_vert[i0], e3);
        atomicAdd(&per_vert[i1], e3);
        atomicAdd(&per_vert[i2], e3);
    }

    // block-reduce e -> one loss atomic per block
    float v = e;
    #pragma unroll
    for (int off = 16; off > 0; off >>= 1)
        v += __shfl_down_sync(0xFFFFFFFFu, v, off);

    __shared__ float smem[8];
    int lane = threadIdx.x & 31;
    int wid = threadIdx.x >> 5;
    if (lane == 0) smem[wid] = v;
    __syncthreads();
    if (wid == 0) {
        float w = (lane < (blockDim.x >> 5)) ? smem[lane] : 0.0f;
        #pragma unroll
        for (int off = 4; off > 0; off >>= 1)
            w += __shfl_down_sync(0xFFFFFFFFu, w, off);
        if (lane == 0 && loss != nullptr)
            atomicAdd(loss, w);
    }
}

extern "C" void kernel_launch(void* const* d_in, const int* in_sizes, int n_in,
                              void* d_out, int out_size) {
    const float* pos = (const float*)d_in[0];
    const int* faces = (const int*)d_in[1];
    const float* dminv = (const float*)d_in[2];
    const float* area = (const float*)d_in[3];
    const float* mu_p = (const float*)d_in[4];
    const float* lam_p = (const float*)d_in[5];

    int V = in_sizes[0] / 3;
    int F = in_sizes[1] / 3;

    float* out = (float*)d_out;
    float* per_vert = out + (out_size - V);
    float* loss = (out_size > V) ? out : nullptr;

    cudaMemsetAsync(d_out, 0, (size_t)out_size * sizeof(float));

    int threads = 256;
    pad_pos_kernel<<<(V + threads - 1) / threads, threads>>>(pos, V);
    stvk_face_kernel<<<(F + threads - 1) / threads, threads>>>(
        faces, dminv, area, mu_p, lam_p, per_vert, loss, F);
}